// round 16
// baseline (speedup 1.0000x reference)
#include <cuda_runtime.h>
#include <cuda_fp16.h>
#include <mma.h>
#include <math.h>

using namespace nvcuda;

#define NN 10000
#define EE 320000
#define INF 256
#define HID 128
#define HEADS 4
#define PAD 32      // counter stride in ints -> one 128B line per counter
#define CAP 96      // max in-degree bucket capacity (Poisson(32): P(>96) ~ 1e-37)
#define GF_BLOCKS 592   // 148 SMs x 4 blocks: co-resident => spin barrier safe

// ---------------- scratch (static device globals; no allocs) ----------------
__device__ int      g_incnt[NN * PAD];
__device__ int      g_outcnt[NN * PAD];
__device__ int      g_esrc[NN * CAP];    // bucketed CSR-by-dst
__device__ float    g_doutf[NN];         // rsqrt(max(outdeg,1)) precomputed
__device__ __half   g_w1h[INF * HID];    // W1 fp16 (converted once)
__device__ __half   g_w2h[HID * HID];    // W2 fp16 (converted once)
__device__ __half   g_t0h[NN * HID];     // gemm output (pre-agg), fp16
__device__ float4   g_el4[NN];
__device__ float4   g_er4[NN];
__device__ float4   g_w4[NN];
__device__ float    g_M[HID][12];        // folded Wg·attn_l | Wg·attn_r | Wg·W3
__device__ float    g_cbg;
__device__ float    g_y[NN];
__device__ unsigned g_bar;               // grid barrier counter (reset in k_prep)

__device__ __forceinline__ float inv_sqrt_deg(int cnt) {
    return rsqrtf(fmaxf((float)cnt, 1.f));
}

// ---------------- weight fp32->fp16 conversion (once, stream 0) --------------
__global__ void __launch_bounds__(256) k_wcvt(const float* __restrict__ W1,
                                              const float* __restrict__ W2) {
    if (blockIdx.x < 32) {
        int i4 = (blockIdx.x * 256 + threadIdx.x) * 4;
        float4 v = *(const float4*)(W1 + i4);
        __half2 h0 = __floats2half2_rn(v.x, v.y);
        __half2 h1 = __floats2half2_rn(v.z, v.w);
        uint2 u; u.x = *(unsigned*)&h0; u.y = *(unsigned*)&h1;
        *(uint2*)(g_w1h + i4) = u;
    } else {
        int i4 = ((blockIdx.x - 32) * 256 + threadIdx.x) * 4;
        float4 v = *(const float4*)(W2 + i4);
        __half2 h0 = __floats2half2_rn(v.x, v.y);
        __half2 h1 = __floats2half2_rn(v.z, v.w);
        uint2 u; u.x = *(unsigned*)&h0; u.y = *(unsigned*)&h1;
        *(uint2*)(g_w2h + i4) = u;
    }
}

// ---------------- precompute M, cbg + zero padded counters + reset barrier ---
__global__ void __launch_bounds__(256) k_prep(const float* __restrict__ Wg,
                                              const float* __restrict__ attn_l,
                                              const float* __restrict__ attn_r,
                                              const float* __restrict__ W3,
                                              const float* __restrict__ bg) {
    int lane = threadIdx.x & 31;
    if (blockIdx.x >= 65) {
        int idx = (blockIdx.x - 65) * 256 + threadIdx.x;
        if (idx < NN) { g_incnt[idx * PAD] = 0; g_outcnt[idx * PAD] = 0; }
        return;
    }
    if (blockIdx.x == 64) {
        if (threadIdx.x == 32) g_bar = 0u;
        if (threadIdx.x < 32) {
            float s = 0.f;
            for (int i = lane; i < HEADS * HID; i += 32) s += bg[i] * W3[i & (HID - 1)];
#pragma unroll
            for (int o = 16; o; o >>= 1) s += __shfl_xor_sync(0xFFFFFFFFu, s, o);
            if (!lane) g_cbg = s;
        }
        return;
    }
    int gw = blockIdx.x * 8 + (threadIdx.x >> 5);
    int k = gw >> 2, h = gw & 3;
    float sl = 0.f, sr = 0.f, sw = 0.f;
    for (int i = lane; i < HID; i += 32) {
        float wv = Wg[(size_t)k * (HEADS * HID) + h * HID + i];
        sl += wv * attn_l[h * HID + i];
        sr += wv * attn_r[h * HID + i];
        sw += wv * W3[i];
    }
#pragma unroll
    for (int o = 16; o; o >>= 1) {
        sl += __shfl_xor_sync(0xFFFFFFFFu, sl, o);
        sr += __shfl_xor_sync(0xFFFFFFFFu, sr, o);
        sw += __shfl_xor_sync(0xFFFFFFFFu, sw, o);
    }
    if (!lane) { g_M[k][h] = sl; g_M[k][4 + h] = sr; g_M[k][8 + h] = sw; }
}

// ---------------- one-pass bucketed CSR build ----------------
__global__ void k_build(const int* __restrict__ src, const int* __restrict__ dst) {
    int e = blockIdx.x * blockDim.x + threadIdx.x;
    if (e >= EE) return;
    int s = src[e], d = dst[e];
    atomicAdd(&g_outcnt[s * PAD], 1);
    int slot = atomicAdd(&g_incnt[d * PAD], 1);
    if (slot < CAP) g_esrc[d * CAP + slot] = s;
}

__global__ void k_dout() {
    int n = blockIdx.x * blockDim.x + threadIdx.x;
    if (n < NN) g_doutf[n] = inv_sqrt_deg(g_outcnt[n * PAD]);
}

// ---------------- WMMA fp16 GEMM1: 32x128 tile, BK=32, 256 thr ---------------
__global__ void __launch_bounds__(256) k_gemm1(const float* __restrict__ Aext) {
    constexpr int K = INF, NIT = K / 32;
    __shared__ __align__(16) char smraw[16384];
    __half (*As)[40]  = reinterpret_cast<__half(*)[40]>(smraw);
    __half (*Bs)[136] = reinterpret_cast<__half(*)[136]>(smraw + 2560);
    float  (*Cs)[128] = reinterpret_cast<float(*)[128]>(smraw);

    int tid = threadIdx.x;
    int warp = tid >> 5;
    int wr = warp & 1, wc = warp >> 1;
    int row0 = blockIdx.x * 32;

    int ar = tid >> 3, akq = (tid & 7) * 4;
    int bkr = tid >> 3, bcb = (tid & 7) * 16;
    bool arow_ok = (row0 + ar) < NN;

    wmma::fragment<wmma::accumulator, 16, 16, 16, float> c0, c1;
    wmma::fill_fragment(c0, 0.f);
    wmma::fill_fragment(c1, 0.f);

    float4 aP = make_float4(0.f, 0.f, 0.f, 0.f);
    uint4  bP0, bP1;
    auto LOAD = [&](int k0) {
        aP = arow_ok ? *(const float4*)(Aext + (size_t)(row0 + ar) * K + k0 + akq)
                     : make_float4(0.f, 0.f, 0.f, 0.f);
        const uint4* wp = (const uint4*)(g_w1h + (size_t)(k0 + bkr) * HID + bcb);
        bP0 = wp[0];
        bP1 = wp[1];
    };

    LOAD(0);
#pragma unroll
    for (int it = 0; it < NIT; it++) {
        if (it) __syncthreads();
        {
            __half2 h0 = __floats2half2_rn(aP.x, aP.y);
            __half2 h1 = __floats2half2_rn(aP.z, aP.w);
            uint2 u; u.x = *(unsigned*)&h0; u.y = *(unsigned*)&h1;
            *(uint2*)&As[ar][akq] = u;
        }
        *(uint4*)&Bs[bkr][bcb] = bP0;
        *(uint4*)&Bs[bkr][bcb + 8] = bP1;
        __syncthreads();
        if (it + 1 < NIT) LOAD((it + 1) * 32);
#pragma unroll
        for (int kk = 0; kk < 32; kk += 16) {
            wmma::fragment<wmma::matrix_a, 16, 16, 16, __half, wmma::row_major> a;
            wmma::fragment<wmma::matrix_b, 16, 16, 16, __half, wmma::row_major> b0, b1;
            wmma::load_matrix_sync(a, &As[wr * 16][kk], 40);
            wmma::load_matrix_sync(b0, &Bs[kk][wc * 32], 136);
            wmma::load_matrix_sync(b1, &Bs[kk][wc * 32 + 16], 136);
            wmma::mma_sync(c0, a, b0, c0);
            wmma::mma_sync(c1, a, b1, c1);
        }
    }
    __syncthreads();
    wmma::store_matrix_sync(&Cs[wr * 16][wc * 32], c0, 128, wmma::mem_row_major);
    wmma::store_matrix_sync(&Cs[wr * 16][wc * 32 + 16], c1, 128, wmma::mem_row_major);
    __syncthreads();
    {
        int r = tid >> 3, cb = (tid & 7) * 16;
        int row = row0 + r;
        if (row < NN) {
            __half2 buf[8];
#pragma unroll
            for (int q = 0; q < 8; q++)
                buf[q] = __floats2half2_rn(Cs[r][cb + q * 2], Cs[r][cb + q * 2 + 1]);
            uint4* op = (uint4*)(g_t0h + (size_t)row * HID + cb);
            const uint4* bp = (const uint4*)buf;
            op[0] = bp[0]; op[1] = bp[1];
        }
    }
}

// ---------------- FUSED agg1 + GEMM2 -----------------------------------------
// Block = 32 nodes. 8 warps x 4 interleaved gather chains -> h1 tile in smem
// (fp16, pre-scaled by dout), then 32x128 WMMA vs g_w2h -> g_t0h.
__global__ void __launch_bounds__(256) k_agg1gemm2(const float* __restrict__ b1) {
    __shared__ __align__(16) char smraw[17408];
    __half (*As)[136] = reinterpret_cast<__half(*)[136]>(smraw);            // h1 tile 32x128(+8)
    __half (*Bs)[136] = reinterpret_cast<__half(*)[136]>(smraw + 8704);     // W2 k-tile
    float  (*Cs)[128] = reinterpret_cast<float(*)[128]>(smraw);             // epilogue alias

    int tid = threadIdx.x;
    int warp = tid >> 5;
    int lane = tid & 31;
    int row0 = blockIdx.x * 32;

    // ---- phase A: aggregate 4 nodes per warp (independent chains) ----
    {
        int n[4], m[4];
        const int* rp[4];
        float4 acc[4];
#pragma unroll
        for (int i = 0; i < 4; i++) {
            n[i] = row0 + warp * 4 + i;
            bool v = n[i] < NN;
            m[i] = v ? min(g_incnt[n[i] * PAD], CAP) : 0;
            rp[i] = g_esrc + (v ? n[i] : 0) * CAP;
            acc[i] = make_float4(0.f, 0.f, 0.f, 0.f);
        }
        int mm = max(max(m[0], m[1]), max(m[2], m[3]));
        for (int j = 0; j < mm; j++) {
#pragma unroll
            for (int i = 0; i < 4; i++) {
                if (j < m[i]) {
                    int s = rp[i][j];
                    float ds = g_doutf[s];
                    const __half2* p = (const __half2*)(g_t0h + (size_t)s * HID + lane * 4);
                    float2 u0 = __half22float2(p[0]);
                    float2 u1 = __half22float2(p[1]);
                    acc[i].x = fmaf(ds, u0.x, acc[i].x);
                    acc[i].y = fmaf(ds, u0.y, acc[i].y);
                    acc[i].z = fmaf(ds, u1.x, acc[i].z);
                    acc[i].w = fmaf(ds, u1.y, acc[i].w);
                }
            }
        }
        float4 bb = *(const float4*)(b1 + lane * 4);
#pragma unroll
        for (int i = 0; i < 4; i++) {
            int r = warp * 4 + i;
            float din = inv_sqrt_deg(m[i]);
            float dn = (n[i] < NN) ? g_doutf[n[i]] : 0.f;
            float ox = fmaxf(acc[i].x * din + bb.x, 0.f) * dn;
            float oy = fmaxf(acc[i].y * din + bb.y, 0.f) * dn;
            float oz = fmaxf(acc[i].z * din + bb.z, 0.f) * dn;
            float ow = fmaxf(acc[i].w * din + bb.w, 0.f) * dn;
            __half2 h0 = __floats2half2_rn(ox, oy);
            __half2 h1 = __floats2half2_rn(oz, ow);
            uint2 u; u.x = *(unsigned*)&h0; u.y = *(unsigned*)&h1;
            *(uint2*)&As[r][lane * 4] = u;
        }
    }
    __syncthreads();

    // ---- phase B: 32x128 GEMM, A(smem) x W2 -> t0h ----
    int wr = warp & 1, wc = warp >> 1;
    int bkr = tid >> 3, bcb = (tid & 7) * 16;

    wmma::fragment<wmma::accumulator, 16, 16, 16, float> c0, c1;
    wmma::fill_fragment(c0, 0.f);
    wmma::fill_fragment(c1, 0.f);

    uint4 bP0, bP1;
    auto LOADB = [&](int k0) {
        const uint4* wp = (const uint4*)(g_w2h + (size_t)(k0 + bkr) * HID + bcb);
        bP0 = wp[0];
        bP1 = wp[1];
    };

    LOADB(0);
#pragma unroll
    for (int it = 0; it < 4; it++) {
        if (it) __syncthreads();
        *(uint4*)&Bs[bkr][bcb] = bP0;
        *(uint4*)&Bs[bkr][bcb + 8] = bP1;
        __syncthreads();
        if (it + 1 < 4) LOADB((it + 1) * 32);
#pragma unroll
        for (int kk = 0; kk < 32; kk += 16) {
            wmma::fragment<wmma::matrix_a, 16, 16, 16, __half, wmma::row_major> a;
            wmma::fragment<wmma::matrix_b, 16, 16, 16, __half, wmma::row_major> b0, b1;
            wmma::load_matrix_sync(a, &As[wr * 16][it * 32 + kk], 136);
            wmma::load_matrix_sync(b0, &Bs[kk][wc * 32], 136);
            wmma::load_matrix_sync(b1, &Bs[kk][wc * 32 + 16], 136);
            wmma::mma_sync(c0, a, b0, c0);
            wmma::mma_sync(c1, a, b1, c1);
        }
    }
    __syncthreads();
    wmma::store_matrix_sync(&Cs[wr * 16][wc * 32], c0, 128, wmma::mem_row_major);
    wmma::store_matrix_sync(&Cs[wr * 16][wc * 32 + 16], c1, 128, wmma::mem_row_major);
    __syncthreads();
    {
        int r = tid >> 3, cb = (tid & 7) * 16;
        int row = row0 + r;
        if (row < NN) {
            __half2 buf[8];
#pragma unroll
            for (int q = 0; q < 8; q++)
                buf[q] = __floats2half2_rn(Cs[r][cb + q * 2], Cs[r][cb + q * 2 + 1]);
            uint4* op = (uint4*)(g_t0h + (size_t)row * HID + cb);
            const uint4* bp = (const uint4*)buf;
            op[0] = bp[0]; op[1] = bp[1];
        }
    }
}

// ---------------- agg2 (2 nodes/warp, R15-proven) + el/er/w projection -------
__global__ void k_agg2(const float* __restrict__ b) {
    int w = (blockIdx.x * blockDim.x + threadIdx.x) >> 5;
    int lane = threadIdx.x & 31;
    int n0 = w * 2, n1 = w * 2 + 1;
    if (n0 >= NN) return;
    bool v1 = n1 < NN;

    int m0 = min(g_incnt[n0 * PAD], CAP);
    int m1 = v1 ? min(g_incnt[n1 * PAD], CAP) : 0;
    const int* r0 = g_esrc + n0 * CAP;
    const int* r1 = g_esrc + (v1 ? n1 : n0) * CAP;
    float4 a0 = make_float4(0.f, 0.f, 0.f, 0.f);
    float4 a1 = make_float4(0.f, 0.f, 0.f, 0.f);
    int mm = max(m0, m1);
#pragma unroll 2
    for (int j = 0; j < mm; j++) {
        if (j < m0) {
            int s = r0[j];
            const __half2* p = (const __half2*)(g_t0h + (size_t)s * HID + lane * 4);
            float2 u0 = __half22float2(p[0]);
            float2 u1 = __half22float2(p[1]);
            a0.x += u0.x; a0.y += u0.y; a0.z += u1.x; a0.w += u1.y;
        }
        if (j < m1) {
            int s = r1[j];
            const __half2* p = (const __half2*)(g_t0h + (size_t)s * HID + lane * 4);
            float2 u0 = __half22float2(p[0]);
            float2 u1 = __half22float2(p[1]);
            a1.x += u0.x; a1.y += u0.y; a1.z += u1.x; a1.w += u1.y;
        }
    }
    float4 bb = *(const float4*)(b + lane * 4);
    float d0 = inv_sqrt_deg(m0);
    float h0[4] = {fmaxf(a0.x * d0 + bb.x, 0.f), fmaxf(a0.y * d0 + bb.y, 0.f),
                   fmaxf(a0.z * d0 + bb.z, 0.f), fmaxf(a0.w * d0 + bb.w, 0.f)};
    float d1 = inv_sqrt_deg(m1);
    float h1[4] = {fmaxf(a1.x * d1 + bb.x, 0.f), fmaxf(a1.y * d1 + bb.y, 0.f),
                   fmaxf(a1.z * d1 + bb.z, 0.f), fmaxf(a1.w * d1 + bb.w, 0.f)};

    float Mr[4][12];
#pragma unroll
    for (int i = 0; i < 4; i++)
#pragma unroll
        for (int j = 0; j < 12; j++) Mr[i][j] = g_M[lane * 4 + i][j];

    float dt0[12], dt1[12];
#pragma unroll
    for (int j = 0; j < 12; j++) {
        float s0 = 0.f, s1 = 0.f;
#pragma unroll
        for (int i = 0; i < 4; i++) {
            s0 = fmaf(h0[i], Mr[i][j], s0);
            s1 = fmaf(h1[i], Mr[i][j], s1);
        }
        dt0[j] = s0; dt1[j] = s1;
    }
#pragma unroll
    for (int off = 16; off; off >>= 1)
#pragma unroll
        for (int j = 0; j < 12; j++) {
            dt0[j] += __shfl_xor_sync(0xFFFFFFFFu, dt0[j], off);
            dt1[j] += __shfl_xor_sync(0xFFFFFFFFu, dt1[j], off);
        }
    if (!lane) {
        g_el4[n0] = make_float4(dt0[0], dt0[1], dt0[2], dt0[3]);
        g_er4[n0] = make_float4(dt0[4], dt0[5], dt0[6], dt0[7]);
        g_w4[n0]  = make_float4(dt0[8], dt0[9], dt0[10], dt0[11]);
        if (v1) {
            g_el4[n1] = make_float4(dt1[0], dt1[1], dt1[2], dt1[3]);
            g_er4[n1] = make_float4(dt1[4], dt1[5], dt1[6], dt1[7]);
            g_w4[n1]  = make_float4(dt1[8], dt1[9], dt1[10], dt1[11]);
        }
    }
}

// ---------------- fused GAT + final conv (software grid barrier) -------------
__global__ void __launch_bounds__(256) k_gatfinal(const float* __restrict__ b3,
                                                  float* __restrict__ out) {
    int lane = threadIdx.x & 31;
    int gwarp = blockIdx.x * 8 + (threadIdx.x >> 5);
    int wstride = GF_BLOCKS * 8;

    for (int d = gwarp; d < NN; d += wstride) {
        int cnt = min(g_incnt[d * PAD], CAP);
        const int* row = g_esrc + d * CAP;
        float4 er = g_er4[d];
        float erh[4] = {er.x, er.y, er.z, er.w};
        float m[4], den[4], aw[4];
#pragma unroll
        for (int h = 0; h < 4; h++) { m[h] = -INFINITY; den[h] = 0.f; aw[h] = 0.f; }
        for (int j = lane; j < cnt; j += 32) {
            int s = row[j];
            float4 el = g_el4[s];
            float4 wv = g_w4[s];
            float elh[4] = {el.x, el.y, el.z, el.w};
            float wh[4] = {wv.x, wv.y, wv.z, wv.w};
#pragma unroll
            for (int h = 0; h < 4; h++) {
                float e = elh[h] + erh[h];
                e = e > 0.f ? e : 0.2f * e;
                float mn = fmaxf(m[h], e);
                float sc = __expf(m[h] - mn);
                float p  = __expf(e - mn);
                den[h] = den[h] * sc + p;
                aw[h]  = aw[h] * sc + p * wh[h];
                m[h] = mn;
            }
        }
#pragma unroll
        for (int off = 16; off; off >>= 1) {
#pragma unroll
            for (int h = 0; h < 4; h++) {
                float m2 = __shfl_xor_sync(0xFFFFFFFFu, m[h], off);
                float d2 = __shfl_xor_sync(0xFFFFFFFFu, den[h], off);
                float a2 = __shfl_xor_sync(0xFFFFFFFFu, aw[h], off);
                float mn = fmaxf(m[h], m2);
                float s1 = (m[h] == mn) ? 1.f : __expf(m[h] - mn);
                float s2 = (m2 == mn) ? 1.f : __expf(m2 - mn);
                den[h] = den[h] * s1 + d2 * s2;
                aw[h]  = aw[h] * s1 + a2 * s2;
                m[h] = mn;
            }
        }
        if (!lane) {
            float s = g_cbg;
#pragma unroll
            for (int h = 0; h < 4; h++) s += (den[h] > 0.f) ? (aw[h] / den[h]) : 0.f;
            g_y[d] = 0.25f * s * g_doutf[d];
        }
    }

    __syncthreads();
    if (threadIdx.x == 0) {
        __threadfence();
        atomicAdd(&g_bar, 1u);
        while (atomicAdd(&g_bar, 0u) < (unsigned)GF_BLOCKS) {}
    }
    __syncthreads();

    for (int n = gwarp; n < NN; n += wstride) {
        int cnt = g_incnt[n * PAD];
        int mm = min(cnt, CAP);
        const int* row = g_esrc + n * CAP;
        float s = 0.f;
        for (int j = lane; j < mm; j += 32) s += g_y[row[j]];
#pragma unroll
        for (int o = 16; o; o >>= 1) s += __shfl_xor_sync(0xFFFFFFFFu, s, o);
        if (!lane) {
            float v = s * inv_sqrt_deg(cnt) + b3[0];
            out[n] = 1.f / (1.f + __expf(-v));
        }
    }
}

// ---------------- launch ----------------
extern "C" void kernel_launch(void* const* d_in, const int* in_sizes, int n_in,
                              void* d_out, int out_size) {
    const float* features = (const float*)d_in[0];
    const int*   src      = (const int*)d_in[1];
    const int*   dst      = (const int*)d_in[2];
    const float* W1       = (const float*)d_in[3];
    const float* b1       = (const float*)d_in[4];
    const float* W2       = (const float*)d_in[5];
    const float* b2       = (const float*)d_in[6];
    const float* W3       = (const float*)d_in[7];
    const float* b3       = (const float*)d_in[8];
    const float* Wg       = (const float*)d_in[9];
    const float* attn_l   = (const float*)d_in[10];
    const float* attn_r   = (const float*)d_in[11];
    const float* bg       = (const float*)d_in[12];
    float* out = (float*)d_out;

    static cudaStream_t s1 = nullptr;
    static cudaEvent_t ev_fork = nullptr, ev_join = nullptr;
    if (s1 == nullptr) {
        cudaStreamCreateWithFlags(&s1, cudaStreamNonBlocking);
        cudaEventCreateWithFlags(&ev_fork, cudaEventDisableTiming);
        cudaEventCreateWithFlags(&ev_join, cudaEventDisableTiming);
    }

    const int TB = 256;
    int ebl = (EE + TB - 1) / TB;
    int nwbl2 = ((NN + 1) / 2 * 32 + TB - 1) / TB;   // 2 nodes per warp: 625
    int rowtiles32 = (NN + 31) / 32;                 // 313

    // fork: s1 builds bucketed CSR (+prep, dout); stream 0: wcvt -> gemm1
    cudaEventRecord(ev_fork, 0);
    cudaStreamWaitEvent(s1, ev_fork, 0);

    k_prep<<<105, 256, 0, s1>>>(Wg, attn_l, attn_r, W3, bg);
    k_build<<<ebl, TB, 0, s1>>>(src, dst);
    k_dout<<<(NN + TB - 1) / TB, TB, 0, s1>>>();

    k_wcvt<<<48, 256>>>(W1, W2);
    k_gemm1<<<rowtiles32, 256>>>(features);

    cudaEventRecord(ev_join, s1);
    cudaStreamWaitEvent(0, ev_join, 0);

    // fused GraphConv1 aggregation + GraphConv2 GEMM (h1 never leaves smem)
    k_agg1gemm2<<<rowtiles32, 256>>>(b1);

    // GraphConv2 aggregation + el/er/w projection
    k_agg2<<<nwbl2, TB>>>(b2);

    // fused GAT + final conv + sigmoid (grid barrier inside)
    k_gatfinal<<<GF_BLOCKS, 256>>>(b3, out);
}